// round 9
// baseline (speedup 1.0000x reference)
#include <cuda_runtime.h>
#include <cstdint>

// Problem constants
#define KC    1024      // codebook size
#define DC    64        // dim
#define NC    131072    // number of vectors
#define GAMMA 0.99f
#define ALPHA 1e-9f
#define BETA  0.25f

// Output layout (float32, concatenated in reference tuple order)
// NOTE: OFF_EN / OFF_MA are NOT 16B-aligned (odd element offsets) — scalar
// stores only in those sections.
#define OFF_Z    0
#define OFF_LOSS 8388608
#define OFF_ARG  8388609
#define OFF_MIN  8519681
#define OFF_EN   8650753
#define OFF_CS   8716289
#define OFF_MA   8717313

// Scratch (device globals: no allocation allowed)
__device__ __align__(16) float g_sums[KC * DC];   // segment sums of X per code
__device__ float g_counts[KC];      // segment counts
__device__ float g_esq[KC];         // ||e_k||^2
__device__ float g_minsum;          // sum of ||x - e_j||^2 (for loss)

// Packed f32x2 helpers (sm_103a FFMA2 path — ptxas never auto-fuses this)
__device__ __forceinline__ uint64_t fma2(uint64_t a, uint64_t b, uint64_t c) {
    uint64_t d;
    asm("fma.rn.f32x2 %0, %1, %2, %3;" : "=l"(d) : "l"(a), "l"(b), "l"(c));
    return d;
}
__device__ __forceinline__ uint64_t add2(uint64_t a, uint64_t b) {
    uint64_t d;
    asm("add.rn.f32x2 %0, %1, %2;" : "=l"(d) : "l"(a), "l"(b));
    return d;
}
__device__ __forceinline__ void unpack2(uint64_t v, float& lo, float& hi) {
    uint32_t l, h;
    asm("mov.b64 {%0, %1}, %2;" : "=r"(l), "=r"(h) : "l"(v));
    lo = __uint_as_float(l);
    hi = __uint_as_float(h);
}

// ---------------------------------------------------------------------------
// Kernel 1: zero scratch + codebook row squared norms (fused)
// ---------------------------------------------------------------------------
__global__ void vq_prep_kernel(const float* __restrict__ E) {
    int i = blockIdx.x * blockDim.x + threadIdx.x;
    g_sums[i] = 0.0f;
    if (i < KC) {
        g_counts[i] = 0.0f;
        const float4* e = reinterpret_cast<const float4*>(E + (size_t)i * DC);
        float s = 0.0f;
#pragma unroll
        for (int j = 0; j < DC / 4; j++) {
            float4 v = e[j];
            s += v.x * v.x + v.y * v.y + v.z * v.z + v.w * v.w;
        }
        g_esq[i] = s;
    }
    if (i == 0) g_minsum = 0.0f;
}

// ---------------------------------------------------------------------------
// Kernel 2: main assignment — one X row per thread (as f32x2 pairs),
// E tiled through smem, FFMA2 inner loop
// ---------------------------------------------------------------------------
#define TPB   256
#define CHUNK 128   // codes per smem tile

__global__ __launch_bounds__(TPB) void vq_assign_kernel(
    const float* __restrict__ X, const float* __restrict__ E,
    float* __restrict__ out)
{
    __shared__ float4 se[CHUNK * (DC / 4)];   // 32 KB
    __shared__ float  sesq[CHUNK];
    __shared__ float  swred[TPB / 32];

    const int row = blockIdx.x * TPB + threadIdx.x;   // grid sized so always < NC

    // Load X row as 32 packed f32x2 pairs
    uint64_t x2[DC / 2];
    const ulonglong2* xp = reinterpret_cast<const ulonglong2*>(X + (size_t)row * DC);
#pragma unroll
    for (int i = 0; i < DC / 4; i++) {
        ulonglong2 t = xp[i];
        x2[2 * i + 0] = t.x;
        x2[2 * i + 1] = t.y;
    }

    // ||x||^2 via packed FMA
    float xsq;
    {
        uint64_t sq[4] = {0, 0, 0, 0};
#pragma unroll
        for (int j = 0; j < DC / 2; j++)
            sq[j & 3] = fma2(x2[j], x2[j], sq[j & 3]);
        uint64_t s = add2(add2(sq[0], sq[1]), add2(sq[2], sq[3]));
        float a, b;
        unpack2(s, a, b);
        xsq = a + b;
    }

    float best = 3.4e38f;
    int   bj   = 0;

    const float4* Ef4 = reinterpret_cast<const float4*>(E);
    for (int c0 = 0; c0 < KC; c0 += CHUNK) {
        __syncthreads();
        // Cooperative load of E chunk + sqnorms into smem
        for (int i = threadIdx.x; i < CHUNK * (DC / 4); i += TPB)
            se[i] = Ef4[c0 * (DC / 4) + i];
        for (int i = threadIdx.x; i < CHUNK; i += TPB)
            sesq[i] = g_esq[c0 + i];
        __syncthreads();

        for (int c = 0; c < CHUNK; c++) {
            const ulonglong2* eb =
                reinterpret_cast<const ulonglong2*>(&se[c * (DC / 4)]);
            uint64_t acc0 = 0, acc1 = 0, acc2 = 0, acc3 = 0;
#pragma unroll
            for (int i = 0; i < DC / 4; i += 2) {
                ulonglong2 e0 = eb[i + 0];
                ulonglong2 e1 = eb[i + 1];
                acc0 = fma2(x2[2 * i + 0], e0.x, acc0);
                acc1 = fma2(x2[2 * i + 1], e0.y, acc1);
                acc2 = fma2(x2[2 * i + 2], e1.x, acc2);
                acc3 = fma2(x2[2 * i + 3], e1.y, acc3);
            }
            uint64_t s = add2(add2(acc0, acc1), add2(acc2, acc3));
            float a, b;
            unpack2(s, a, b);
            float dot   = a + b;
            float proxy = fmaf(-2.0f, dot, sesq[c]);   // dist - ||x||^2
            if (proxy < best) { best = proxy; bj = c0 + c; }
        }
    }

    float mind = xsq + best;

    // Unpack X row to scalars for epilogue (once; amortized over 1024 codes)
    float xf[DC];
#pragma unroll
    for (int j = 0; j < DC / 2; j++)
        unpack2(x2[j], xf[2 * j], xf[2 * j + 1]);

    // Z row = E[bj], exact squared distance for the loss, scatter sums
    const float4* ep = reinterpret_cast<const float4*>(E + (size_t)bj * DC);
    float4* zp = reinterpret_cast<float4*>(out + OFF_Z + (size_t)row * DC);
    float* sp  = g_sums + (size_t)bj * DC;
    float ls = 0.0f;
#pragma unroll
    for (int i = 0; i < DC / 4; i++) {
        float4 ev = ep[i];
        zp[i] = ev;
        float dx = xf[i * 4 + 0] - ev.x, dy = xf[i * 4 + 1] - ev.y;
        float dz = xf[i * 4 + 2] - ev.z, dw = xf[i * 4 + 3] - ev.w;
        ls += dx * dx + dy * dy + dz * dz + dw * dw;
        atomicAdd(sp + i * 4 + 0, xf[i * 4 + 0]);
        atomicAdd(sp + i * 4 + 1, xf[i * 4 + 1]);
        atomicAdd(sp + i * 4 + 2, xf[i * 4 + 2]);
        atomicAdd(sp + i * 4 + 3, xf[i * 4 + 3]);
    }
    atomicAdd(&g_counts[bj], 1.0f);

    out[OFF_ARG + row] = (float)bj;
    out[OFF_MIN + row] = mind;

    // Loss reduction: warp shuffle, then one atomic per block
    const int lane = threadIdx.x & 31;
    const int warp = threadIdx.x >> 5;
#pragma unroll
    for (int s = 16; s > 0; s >>= 1)
        ls += __shfl_xor_sync(0xFFFFFFFFu, ls, s);
    if (lane == 0) swred[warp] = ls;
    __syncthreads();
    if (warp == 0) {
        float v = (lane < TPB / 32) ? swred[lane] : 0.0f;
#pragma unroll
        for (int s = 4; s > 0; s >>= 1)
            v += __shfl_xor_sync(0xFFFFFFFFu, v, s);
        if (lane == 0) atomicAdd(&g_minsum, v);
    }
}

// ---------------------------------------------------------------------------
// Kernel 3: EMA finalize — cs, ma, E_new, loss (one block of KC threads)
// EN/MA output sections are 4B-aligned only -> scalar stores there.
// ---------------------------------------------------------------------------
__global__ void vq_finalize_kernel(
    const float* __restrict__ cluster_sizes,
    const float* __restrict__ moving_avg,
    float* __restrict__ out)
{
    __shared__ float red[KC];
    const int k = threadIdx.x;

    float c = GAMMA * cluster_sizes[k] + (1.0f - GAMMA) * g_counts[k];
    red[k] = c;
    __syncthreads();
    for (int s = KC / 2; s > 0; s >>= 1) {
        if (k < s) red[k] += red[k + s];
        __syncthreads();
    }
    float scs = red[0];

    float cs  = (c + ALPHA) / (1.0f + ALPHA * (float)KC / scs);
    out[OFF_CS + k] = cs;
    float inv = 1.0f / cs;

    const float4* mav = reinterpret_cast<const float4*>(moving_avg + (size_t)k * DC);
    const float4* sv  = reinterpret_cast<const float4*>(g_sums + (size_t)k * DC);
    float* map = out + OFF_MA + (size_t)k * DC;
    float* enp = out + OFF_EN + (size_t)k * DC;
#pragma unroll
    for (int i = 0; i < DC / 4; i++) {
        float4 m = mav[i];
        float4 s4 = sv[i];
        float max_ = GAMMA * m.x + (1.0f - GAMMA) * s4.x;
        float may_ = GAMMA * m.y + (1.0f - GAMMA) * s4.y;
        float maz_ = GAMMA * m.z + (1.0f - GAMMA) * s4.z;
        float maw_ = GAMMA * m.w + (1.0f - GAMMA) * s4.w;
        map[i * 4 + 0] = max_;
        map[i * 4 + 1] = may_;
        map[i * 4 + 2] = maz_;
        map[i * 4 + 3] = maw_;
        enp[i * 4 + 0] = max_ * inv;
        enp[i * 4 + 1] = may_ * inv;
        enp[i * 4 + 2] = maz_ * inv;
        enp[i * 4 + 3] = maw_ * inv;
    }

    if (k == 0) out[OFF_LOSS] = BETA * g_minsum / (float)NC;
}

// ---------------------------------------------------------------------------
// Launch
// ---------------------------------------------------------------------------
extern "C" void kernel_launch(void* const* d_in, const int* in_sizes, int n_in,
                              void* d_out, int out_size)
{
    const float* X  = (const float*)d_in[0];
    const float* E  = (const float*)d_in[1];
    const float* CS = (const float*)d_in[2];
    const float* MA = (const float*)d_in[3];
    float* out = (float*)d_out;

    // Zero scratch + codebook sqnorms (covers KC*DC = 65536 elements)
    vq_prep_kernel<<<KC * DC / 1024, 1024>>>(E);
    // Main assignment
    vq_assign_kernel<<<NC / TPB, TPB>>>(X, E, out);
    // EMA finalize
    vq_finalize_kernel<<<1, KC>>>(CS, MA, out);
}

// round 12
// speedup vs baseline: 1.9372x; 1.9372x over previous
#include <cuda_runtime.h>
#include <cuda_bf16.h>
#include <cstdint>

// Problem constants
#define KC    1024
#define DC    64
#define NC    131072
#define GAMMA 0.99f
#define ALPHA 1e-9f
#define BETA  0.25f

// Output layout (float32, concatenated in reference tuple order)
// OFF_EN / OFF_MA are NOT 16B-aligned -> scalar stores only there.
#define OFF_Z    0
#define OFF_LOSS 8388608
#define OFF_ARG  8388609
#define OFF_MIN  8519681
#define OFF_EN   8650753
#define OFF_CS   8716289
#define OFF_MA   8717313

#define TILE_M   128
#define NTILES   (NC / TILE_M)        // 1024 CTAs
#define ATPB     256                  // 8 warps
#define CH_K     128                  // codes per E chunk
#define NCHUNKS  (KC / CH_K)          // 8
#define ROWW     36                   // padded smem row stride in u32 (72 bf16)

// Device scratch (no allocation allowed)
__device__ __align__(16) float g_sums[KC * DC];
__device__ float g_counts[KC];
__device__ float g_esq[KC];
__device__ float g_minsum;
// E bf16 split images, row-major [code][d], packed 2 bf16 per u32
__device__ __align__(16) uint32_t g_ebf_hi[KC * DC / 2];
__device__ __align__(16) uint32_t g_ebf_lo[KC * DC / 2];

__device__ __forceinline__ void split2(float v, uint16_t& h, uint16_t& l) {
    __nv_bfloat16 hh = __float2bfloat16(v);
    __nv_bfloat16 ll = __float2bfloat16(v - __bfloat162float(hh));
    h = __bfloat16_as_ushort(hh);
    l = __bfloat16_as_ushort(ll);
}
__device__ __forceinline__ uint32_t pack_split(float2 v, uint32_t& lo) {
    uint16_t h0, l0, h1, l1;
    split2(v.x, h0, l0); split2(v.y, h1, l1);
    lo = (uint32_t)l0 | ((uint32_t)l1 << 16);
    return (uint32_t)h0 | ((uint32_t)h1 << 16);
}

// m16n8k16 bf16 MMA, f32 accumulate (base PTX, sm_80+; SASS = HMMA)
__device__ __forceinline__ void mma16816(float& c0, float& c1, float& c2, float& c3,
                                         uint32_t a0, uint32_t a1, uint32_t a2, uint32_t a3,
                                         uint32_t b0, uint32_t b1) {
    asm volatile(
        "mma.sync.aligned.m16n8k16.row.col.f32.bf16.bf16.f32 "
        "{%0,%1,%2,%3}, {%4,%5,%6,%7}, {%8,%9}, {%0,%1,%2,%3};"
        : "+f"(c0), "+f"(c1), "+f"(c2), "+f"(c3)
        : "r"(a0), "r"(a1), "r"(a2), "r"(a3), "r"(b0), "r"(b1));
}

// ---------------------------------------------------------------------------
// Kernel 1: prep — zero scratch, esq, E bf16 split images. 64 x 1024.
// ---------------------------------------------------------------------------
__global__ void vq_prep(const float* __restrict__ E) {
    int i = blockIdx.x * blockDim.x + threadIdx.x;   // [0, 65536)
    g_sums[i] = 0.0f;
    if (i == 0) g_minsum = 0.0f;
    if (i < KC) {
        g_counts[i] = 0.0f;
        const float4* e = reinterpret_cast<const float4*>(E + (size_t)i * DC);
        float s = 0.0f;
#pragma unroll
        for (int j = 0; j < DC / 4; j++) {
            float4 v = e[j];
            s += v.x * v.x + v.y * v.y + v.z * v.z + v.w * v.w;
        }
        g_esq[i] = s;
    }
    if (i < KC * DC / 2) {               // 32768 pairs
        const float2* e2 = reinterpret_cast<const float2*>(E);
        uint32_t lo;
        uint32_t hi = pack_split(e2[i], lo);
        g_ebf_hi[i] = hi;
        g_ebf_lo[i] = lo;
    }
}

// ---------------------------------------------------------------------------
// Kernel 2: assignment via mma.sync — 128 rows/CTA, 8 warps x m16,
// bf16 hi/lo 3-pass, in-register top-2 argmin + fp32-exact recheck
// ---------------------------------------------------------------------------
__global__ void __launch_bounds__(ATPB, 2)
vq_assign_mma(const float* __restrict__ X, const float* __restrict__ E,
              float* __restrict__ out)
{
    __shared__ uint32_t seh[CH_K * ROWW];       // 18432 B
    __shared__ uint32_t sel[CH_K * ROWW];       // 18432 B
    __shared__ float    sesq[KC];               // 4096 B
    __shared__ int      sbj[TILE_M];
    __shared__ int      sbj2[TILE_M];
    __shared__ float    swred[ATPB / 32];

    const int tid  = threadIdx.x;
    const int tile = blockIdx.x;
    const int wid  = tid >> 5;
    const int lane = tid & 31;
    const int g    = lane >> 2;        // groupID: 0..7
    const int q    = lane & 3;         // thread-in-group

    // esq -> smem
    for (int i = tid; i < KC; i += ATPB) sesq[i] = g_esq[i];

    // A fragments: split/pack X rows straight from global.
    // row_lo = tile*128 + wid*16 + g ; row_hi = +8
    const int rl = tile * TILE_M + wid * 16 + g;
    const int rh = rl + 8;
    uint32_t xh[4][4], xl[4][4];
    {
        const float2* X2 = reinterpret_cast<const float2*>(X);
#pragma unroll
        for (int ks = 0; ks < 4; ks++) {
            int k0 = ks * 8 + q;       // float2 index within row (k = 2*that)
            xh[ks][0] = pack_split(X2[(size_t)rl * 32 + k0],     xl[ks][0]);
            xh[ks][1] = pack_split(X2[(size_t)rh * 32 + k0],     xl[ks][1]);
            xh[ks][2] = pack_split(X2[(size_t)rl * 32 + k0 + 4], xl[ks][2]);
            xh[ks][3] = pack_split(X2[(size_t)rh * 32 + k0 + 4], xl[ks][3]);
        }
    }

    // top-2 per owned row (lo / hi)
    float bL1 = 3.4e38f, bL2 = 3.4e38f, bH1 = 3.4e38f, bH2 = 3.4e38f;
    int   jL1 = 0, jL2 = 0, jH1 = 0, jH2 = 0;

    const uint4* gEh = reinterpret_cast<const uint4*>(g_ebf_hi);
    const uint4* gEl = reinterpret_cast<const uint4*>(g_ebf_lo);

    for (int cc = 0; cc < NCHUNKS; cc++) {
        __syncthreads();
        // stage E chunk into padded smem (conflict-free rows of 144 B)
        for (int i = tid; i < CH_K * 8; i += ATPB) {
            int row = i >> 3, qq = i & 7;
            uint4 vh = gEh[(size_t)(cc * CH_K + row) * 8 + qq];
            uint4 vl = gEl[(size_t)(cc * CH_K + row) * 8 + qq];
            *reinterpret_cast<uint4*>(&seh[row * ROWW + qq * 4]) = vh;
            *reinterpret_cast<uint4*>(&sel[row * ROWW + qq * 4]) = vl;
        }
        __syncthreads();

        for (int nt = 0; nt < CH_K / 8; nt++) {
            const uint32_t* bh_row = &seh[(nt * 8 + g) * ROWW];
            const uint32_t* bl_row = &sel[(nt * 8 + g) * ROWW];
            uint32_t bh[8], bl[8];
#pragma unroll
            for (int ks = 0; ks < 4; ks++) {
                int w = ks * 8 + q;
                bh[2 * ks]     = bh_row[w];
                bh[2 * ks + 1] = bh_row[w + 4];
                bl[2 * ks]     = bl_row[w];
                bl[2 * ks + 1] = bl_row[w + 4];
            }
            float c0 = 0.0f, c1 = 0.0f, c2 = 0.0f, c3 = 0.0f;
#pragma unroll
            for (int ks = 0; ks < 4; ks++)
                mma16816(c0, c1, c2, c3, xh[ks][0], xh[ks][1], xh[ks][2], xh[ks][3],
                         bh[2 * ks], bh[2 * ks + 1]);
#pragma unroll
            for (int ks = 0; ks < 4; ks++)
                mma16816(c0, c1, c2, c3, xl[ks][0], xl[ks][1], xl[ks][2], xl[ks][3],
                         bh[2 * ks], bh[2 * ks + 1]);
#pragma unroll
            for (int ks = 0; ks < 4; ks++)
                mma16816(c0, c1, c2, c3, xh[ks][0], xh[ks][1], xh[ks][2], xh[ks][3],
                         bl[2 * ks], bl[2 * ks + 1]);

            int col0 = cc * CH_K + nt * 8 + q * 2;
            int col1 = col0 + 1;
            float p;
            p = fmaf(-2.0f, c0, sesq[col0]);
            if (p < bL1) { bL2 = bL1; jL2 = jL1; bL1 = p; jL1 = col0; }
            else if (p < bL2) { bL2 = p; jL2 = col0; }
            p = fmaf(-2.0f, c1, sesq[col1]);
            if (p < bL1) { bL2 = bL1; jL2 = jL1; bL1 = p; jL1 = col1; }
            else if (p < bL2) { bL2 = p; jL2 = col1; }
            p = fmaf(-2.0f, c2, sesq[col0]);
            if (p < bH1) { bH2 = bH1; jH2 = jH1; bH1 = p; jH1 = col0; }
            else if (p < bH2) { bH2 = p; jH2 = col0; }
            p = fmaf(-2.0f, c3, sesq[col1]);
            if (p < bH1) { bH2 = bH1; jH2 = jH1; bH1 = p; jH1 = col1; }
            else if (p < bH2) { bH2 = p; jH2 = col1; }
        }
    }

    // merge top-2 across the 4 lanes sharing each row (quad = lanes 4g..4g+3)
#pragma unroll
    for (int d = 1; d <= 2; d <<= 1) {
        float o1, o2; int oj1, oj2;
        o1 = __shfl_xor_sync(0xFFFFFFFFu, bL1, d); oj1 = __shfl_xor_sync(0xFFFFFFFFu, jL1, d);
        o2 = __shfl_xor_sync(0xFFFFFFFFu, bL2, d); oj2 = __shfl_xor_sync(0xFFFFFFFFu, jL2, d);
        if (o1 < bL1) { float t = bL1; bL1 = o1; o1 = t; int ti = jL1; jL1 = oj1; oj1 = ti; }
        if (o1 < bL2) { bL2 = o1; jL2 = oj1; }
        if (o2 < bL2) { bL2 = o2; jL2 = oj2; }
        o1 = __shfl_xor_sync(0xFFFFFFFFu, bH1, d); oj1 = __shfl_xor_sync(0xFFFFFFFFu, jH1, d);
        o2 = __shfl_xor_sync(0xFFFFFFFFu, bH2, d); oj2 = __shfl_xor_sync(0xFFFFFFFFu, jH2, d);
        if (o1 < bH1) { float t = bH1; bH1 = o1; o1 = t; int ti = jH1; jH1 = oj1; oj1 = ti; }
        if (o1 < bH2) { bH2 = o1; jH2 = oj1; }
        if (o2 < bH2) { bH2 = o2; jH2 = oj2; }
    }
    if (q == 0) {
        int base = wid * 16 + g;
        sbj[base]      = jL1;  sbj2[base]     = jL2;
        sbj[base + 8]  = jH1;  sbj2[base + 8] = jH2;
    }
    __syncthreads();

    // ---- fp32-exact recheck + outputs: threads 0..127 own one row each ----
    float ls = 0.0f;
    if (tid < TILE_M) {
        const int row = tile * TILE_M + tid;
        int bj = sbj[tid], bj2 = sbj2[tid];
        const float4* xr = reinterpret_cast<const float4*>(X + (size_t)row * DC);
        const float4* e1 = reinterpret_cast<const float4*>(E + (size_t)bj * DC);
        const float4* e2 = reinterpret_cast<const float4*>(E + (size_t)bj2 * DC);
        float4 xf[DC / 4];
        float xsq = 0.0f, dot1 = 0.0f, dot2 = 0.0f;
#pragma unroll
        for (int i = 0; i < DC / 4; i++) {
            float4 xv = xr[i]; xf[i] = xv;
            float4 a = e1[i], b = e2[i];
            xsq  += xv.x * xv.x + xv.y * xv.y + xv.z * xv.z + xv.w * xv.w;
            dot1 += xv.x * a.x + xv.y * a.y + xv.z * a.z + xv.w * a.w;
            dot2 += xv.x * b.x + xv.y * b.y + xv.z * b.z + xv.w * b.w;
        }
        float d1 = fmaf(-2.0f, dot1, sesq[bj]);
        float d2 = fmaf(-2.0f, dot2, sesq[bj2]);
        if (d2 < d1 || (d2 == d1 && bj2 < bj)) { bj = bj2; d1 = d2; }
        float mind = xsq + d1;

        const float4* ef = reinterpret_cast<const float4*>(E + (size_t)bj * DC);
        float4* zp = reinterpret_cast<float4*>(out + OFF_Z + (size_t)row * DC);
        float* sp = g_sums + (size_t)bj * DC;
#pragma unroll
        for (int i = 0; i < DC / 4; i++) {
            float4 ev = ef[i];
            zp[i] = ev;
            float dx = xf[i].x - ev.x, dy = xf[i].y - ev.y;
            float dz = xf[i].z - ev.z, dw = xf[i].w - ev.w;
            ls += dx * dx + dy * dy + dz * dz + dw * dw;
            atomicAdd(sp + i * 4 + 0, xf[i].x);
            atomicAdd(sp + i * 4 + 1, xf[i].y);
            atomicAdd(sp + i * 4 + 2, xf[i].z);
            atomicAdd(sp + i * 4 + 3, xf[i].w);
        }
        atomicAdd(&g_counts[bj], 1.0f);

        out[OFF_ARG + row] = (float)bj;
        out[OFF_MIN + row] = mind;
    }

    // loss reduction over all 256 threads (upper half contributes 0)
#pragma unroll
    for (int s = 16; s > 0; s >>= 1)
        ls += __shfl_xor_sync(0xFFFFFFFFu, ls, s);
    if (lane == 0) swred[wid] = ls;
    __syncthreads();
    if (wid == 0) {
        float v = (lane < ATPB / 32) ? swred[lane] : 0.0f;
#pragma unroll
        for (int s = 4; s > 0; s >>= 1)
            v += __shfl_xor_sync(0xFFFFFFFFu, v, s);
        if (lane == 0) atomicAdd(&g_minsum, v);
    }
}

// ---------------------------------------------------------------------------
// Kernel 3: EMA finalize — cs, ma, E_new, loss (one block of KC threads)
// ---------------------------------------------------------------------------
__global__ void vq_finalize_kernel(
    const float* __restrict__ cluster_sizes,
    const float* __restrict__ moving_avg,
    float* __restrict__ out)
{
    __shared__ float red[KC];
    const int k = threadIdx.x;

    float c = GAMMA * cluster_sizes[k] + (1.0f - GAMMA) * g_counts[k];
    red[k] = c;
    __syncthreads();
    for (int s = KC / 2; s > 0; s >>= 1) {
        if (k < s) red[k] += red[k + s];
        __syncthreads();
    }
    float scs = red[0];

    float cs = (c + ALPHA) / (1.0f + ALPHA * (float)KC / scs);
    out[OFF_CS + k] = cs;
    float inv = 1.0f / cs;

    const float4* mav = reinterpret_cast<const float4*>(moving_avg + (size_t)k * DC);
    const float4* sv  = reinterpret_cast<const float4*>(g_sums + (size_t)k * DC);
    float* map = out + OFF_MA + (size_t)k * DC;
    float* enp = out + OFF_EN + (size_t)k * DC;
#pragma unroll
    for (int i = 0; i < DC / 4; i++) {
        float4 m = mav[i];
        float4 s4 = sv[i];
        float a  = GAMMA * m.x + (1.0f - GAMMA) * s4.x;
        float b  = GAMMA * m.y + (1.0f - GAMMA) * s4.y;
        float cz = GAMMA * m.z + (1.0f - GAMMA) * s4.z;
        float d  = GAMMA * m.w + (1.0f - GAMMA) * s4.w;
        map[i * 4 + 0] = a;  map[i * 4 + 1] = b;
        map[i * 4 + 2] = cz; map[i * 4 + 3] = d;
        enp[i * 4 + 0] = a * inv;  enp[i * 4 + 1] = b * inv;
        enp[i * 4 + 2] = cz * inv; enp[i * 4 + 3] = d * inv;
    }

    if (k == 0) out[OFF_LOSS] = BETA * g_minsum / (float)NC;
}

// ---------------------------------------------------------------------------
// Launch
// ---------------------------------------------------------------------------
extern "C" void kernel_launch(void* const* d_in, const int* in_sizes, int n_in,
                              void* d_out, int out_size)
{
    const float* X  = (const float*)d_in[0];
    const float* E  = (const float*)d_in[1];
    const float* CS = (const float*)d_in[2];
    const float* MA = (const float*)d_in[3];
    float* out = (float*)d_out;

    vq_prep<<<64, 1024>>>(E);
    vq_assign_mma<<<NTILES, ATPB>>>(X, E, out);
    vq_finalize_kernel<<<1, KC>>>(CS, MA, out);
}

// round 14
// speedup vs baseline: 1.9906x; 1.0276x over previous
#include <cuda_runtime.h>
#include <cuda_bf16.h>
#include <cstdint>

// Problem constants
#define KC    1024
#define DC    64
#define NC    131072
#define GAMMA 0.99f
#define ALPHA 1e-9f
#define BETA  0.25f

// Output layout (float32, concatenated in reference tuple order)
// OFF_EN / OFF_MA are NOT 16B-aligned -> scalar stores only there.
#define OFF_Z    0
#define OFF_LOSS 8388608
#define OFF_ARG  8388609
#define OFF_MIN  8519681
#define OFF_EN   8650753
#define OFF_CS   8716289
#define OFF_MA   8717313

#define TILE_M   128
#define NTILES   (NC / TILE_M)        // 1024 CTAs
#define ATPB     256                  // 8 warps
#define CH_K     128                  // codes per E chunk
#define NCHUNKS  (KC / CH_K)          // 8
#define ROWW     36                   // padded smem row stride in u32 (72 bf16)

// Device scratch (no allocation allowed)
__device__ __align__(16) float g_sums[KC * DC];
__device__ float g_counts[KC];
__device__ float g_esq[KC];
__device__ float g_minsum;
// E bf16 split images, row-major [code][d], packed 2 bf16 per u32
__device__ __align__(16) uint32_t g_ebf_hi[KC * DC / 2];
__device__ __align__(16) uint32_t g_ebf_lo[KC * DC / 2];

__device__ __forceinline__ void split2(float v, uint16_t& h, uint16_t& l) {
    __nv_bfloat16 hh = __float2bfloat16(v);
    __nv_bfloat16 ll = __float2bfloat16(v - __bfloat162float(hh));
    h = __bfloat16_as_ushort(hh);
    l = __bfloat16_as_ushort(ll);
}
__device__ __forceinline__ uint32_t pack_split(float2 v, uint32_t& lo) {
    uint16_t h0, l0, h1, l1;
    split2(v.x, h0, l0); split2(v.y, h1, l1);
    lo = (uint32_t)l0 | ((uint32_t)l1 << 16);
    return (uint32_t)h0 | ((uint32_t)h1 << 16);
}

// m16n8k16 bf16 MMA, f32 accumulate (base PTX, sm_80+; SASS = HMMA)
__device__ __forceinline__ void mma16816(float& c0, float& c1, float& c2, float& c3,
                                         uint32_t a0, uint32_t a1, uint32_t a2, uint32_t a3,
                                         uint32_t b0, uint32_t b1) {
    asm volatile(
        "mma.sync.aligned.m16n8k16.row.col.f32.bf16.bf16.f32 "
        "{%0,%1,%2,%3}, {%4,%5,%6,%7}, {%8,%9}, {%0,%1,%2,%3};"
        : "+f"(c0), "+f"(c1), "+f"(c2), "+f"(c3)
        : "r"(a0), "r"(a1), "r"(a2), "r"(a3), "r"(b0), "r"(b1));
}

// ---------------------------------------------------------------------------
// Kernel 1: prep — zero scratch, esq, E bf16 split images. 64 x 1024.
// ---------------------------------------------------------------------------
__global__ void vq_prep(const float* __restrict__ E) {
    int i = blockIdx.x * blockDim.x + threadIdx.x;   // [0, 65536)
    g_sums[i] = 0.0f;
    if (i == 0) g_minsum = 0.0f;
    if (i < KC) {
        g_counts[i] = 0.0f;
        const float4* e = reinterpret_cast<const float4*>(E + (size_t)i * DC);
        float s = 0.0f;
#pragma unroll
        for (int j = 0; j < DC / 4; j++) {
            float4 v = e[j];
            s += v.x * v.x + v.y * v.y + v.z * v.z + v.w * v.w;
        }
        g_esq[i] = s;
    }
    if (i < KC * DC / 2) {               // 32768 pairs
        const float2* e2 = reinterpret_cast<const float2*>(E);
        uint32_t lo;
        uint32_t hi = pack_split(e2[i], lo);
        g_ebf_hi[i] = hi;
        g_ebf_lo[i] = lo;
    }
}

// ---------------------------------------------------------------------------
// Kernel 2: assignment via mma.sync — 128 rows/CTA, 8 warps x m16,
// bf16 hi/lo 3-pass with INDEPENDENT accumulator groups + B prefetch,
// in-register top-2 argmin + fp32-exact recheck
// ---------------------------------------------------------------------------
__global__ void __launch_bounds__(ATPB, 2)
vq_assign_mma(const float* __restrict__ X, const float* __restrict__ E,
              float* __restrict__ out)
{
    __shared__ uint32_t seh[CH_K * ROWW];       // 18432 B
    __shared__ uint32_t sel[CH_K * ROWW];       // 18432 B
    __shared__ float    sesq[KC];               // 4096 B
    __shared__ int      sbj[TILE_M];
    __shared__ int      sbj2[TILE_M];
    __shared__ float    swred[ATPB / 32];

    const int tid  = threadIdx.x;
    const int tile = blockIdx.x;
    const int wid  = tid >> 5;
    const int lane = tid & 31;
    const int g    = lane >> 2;        // groupID: 0..7
    const int q    = lane & 3;         // thread-in-group

    // esq -> smem
    for (int i = tid; i < KC; i += ATPB) sesq[i] = g_esq[i];

    // A fragments: split/pack X rows straight from global.
    const int rl = tile * TILE_M + wid * 16 + g;
    const int rh = rl + 8;
    uint32_t xh[4][4], xl[4][4];
    {
        const float2* X2 = reinterpret_cast<const float2*>(X);
#pragma unroll
        for (int ks = 0; ks < 4; ks++) {
            int k0 = ks * 8 + q;       // float2 index within row
            xh[ks][0] = pack_split(X2[(size_t)rl * 32 + k0],     xl[ks][0]);
            xh[ks][1] = pack_split(X2[(size_t)rh * 32 + k0],     xl[ks][1]);
            xh[ks][2] = pack_split(X2[(size_t)rl * 32 + k0 + 4], xl[ks][2]);
            xh[ks][3] = pack_split(X2[(size_t)rh * 32 + k0 + 4], xl[ks][3]);
        }
    }

    // top-2 per owned row (lo / hi)
    float bL1 = 3.4e38f, bL2 = 3.4e38f, bH1 = 3.4e38f, bH2 = 3.4e38f;
    int   jL1 = 0, jL2 = 0, jH1 = 0, jH2 = 0;

    const uint4* gEh = reinterpret_cast<const uint4*>(g_ebf_hi);
    const uint4* gEl = reinterpret_cast<const uint4*>(g_ebf_lo);

    for (int cc = 0; cc < NCHUNKS; cc++) {
        __syncthreads();
        // stage E chunk into padded smem (conflict-free rows of 144 B)
        for (int i = tid; i < CH_K * 8; i += ATPB) {
            int row = i >> 3, qq = i & 7;
            uint4 vh = gEh[(size_t)(cc * CH_K + row) * 8 + qq];
            uint4 vl = gEl[(size_t)(cc * CH_K + row) * 8 + qq];
            *reinterpret_cast<uint4*>(&seh[row * ROWW + qq * 4]) = vh;
            *reinterpret_cast<uint4*>(&sel[row * ROWW + qq * 4]) = vl;
        }
        __syncthreads();

        // double-buffered B fragments (prefetch next n-tile during MMAs)
        uint32_t bh[2][8], bl[2][8];
        {
            const uint32_t* bhr = &seh[g * ROWW];
            const uint32_t* blr = &sel[g * ROWW];
#pragma unroll
            for (int ks = 0; ks < 4; ks++) {
                int w = ks * 8 + q;
                bh[0][2 * ks]     = bhr[w];
                bh[0][2 * ks + 1] = bhr[w + 4];
                bl[0][2 * ks]     = blr[w];
                bl[0][2 * ks + 1] = blr[w + 4];
            }
        }

#pragma unroll 4
        for (int nt = 0; nt < CH_K / 8; nt++) {
            const int cur = nt & 1, nxt = cur ^ 1;
            if (nt < CH_K / 8 - 1) {
                const uint32_t* bhr = &seh[((nt + 1) * 8 + g) * ROWW];
                const uint32_t* blr = &sel[((nt + 1) * 8 + g) * ROWW];
#pragma unroll
                for (int ks = 0; ks < 4; ks++) {
                    int w = ks * 8 + q;
                    bh[nxt][2 * ks]     = bhr[w];
                    bh[nxt][2 * ks + 1] = bhr[w + 4];
                    bl[nxt][2 * ks]     = blr[w];
                    bl[nxt][2 * ks + 1] = blr[w + 4];
                }
            }

            // 3 independent accumulator groups, interleaved issue
            float a0 = 0.f, a1 = 0.f, a2 = 0.f, a3 = 0.f;   // xh*eh
            float b0 = 0.f, b1 = 0.f, b2 = 0.f, b3 = 0.f;   // xl*eh
            float d0 = 0.f, d1 = 0.f, d2 = 0.f, d3 = 0.f;   // xh*el
#pragma unroll
            for (int ks = 0; ks < 4; ks++) {
                mma16816(a0, a1, a2, a3, xh[ks][0], xh[ks][1], xh[ks][2], xh[ks][3],
                         bh[cur][2 * ks], bh[cur][2 * ks + 1]);
                mma16816(b0, b1, b2, b3, xl[ks][0], xl[ks][1], xl[ks][2], xl[ks][3],
                         bh[cur][2 * ks], bh[cur][2 * ks + 1]);
                mma16816(d0, d1, d2, d3, xh[ks][0], xh[ks][1], xh[ks][2], xh[ks][3],
                         bl[cur][2 * ks], bl[cur][2 * ks + 1]);
            }
            float c0 = a0 + b0 + d0;
            float c1 = a1 + b1 + d1;
            float c2 = a2 + b2 + d2;
            float c3 = a3 + b3 + d3;

            int col0 = cc * CH_K + nt * 8 + q * 2;
            int col1 = col0 + 1;
            float p;
            p = fmaf(-2.0f, c0, sesq[col0]);
            if (p < bL1) { bL2 = bL1; jL2 = jL1; bL1 = p; jL1 = col0; }
            else if (p < bL2) { bL2 = p; jL2 = col0; }
            p = fmaf(-2.0f, c1, sesq[col1]);
            if (p < bL1) { bL2 = bL1; jL2 = jL1; bL1 = p; jL1 = col1; }
            else if (p < bL2) { bL2 = p; jL2 = col1; }
            p = fmaf(-2.0f, c2, sesq[col0]);
            if (p < bH1) { bH2 = bH1; jH2 = jH1; bH1 = p; jH1 = col0; }
            else if (p < bH2) { bH2 = p; jH2 = col0; }
            p = fmaf(-2.0f, c3, sesq[col1]);
            if (p < bH1) { bH2 = bH1; jH2 = jH1; bH1 = p; jH1 = col1; }
            else if (p < bH2) { bH2 = p; jH2 = col1; }
        }
    }

    // merge top-2 across the 4 lanes sharing each row
#pragma unroll
    for (int d = 1; d <= 2; d <<= 1) {
        float o1, o2; int oj1, oj2;
        o1 = __shfl_xor_sync(0xFFFFFFFFu, bL1, d); oj1 = __shfl_xor_sync(0xFFFFFFFFu, jL1, d);
        o2 = __shfl_xor_sync(0xFFFFFFFFu, bL2, d); oj2 = __shfl_xor_sync(0xFFFFFFFFu, jL2, d);
        if (o1 < bL1) { float t = bL1; bL1 = o1; o1 = t; int ti = jL1; jL1 = oj1; oj1 = ti; }
        if (o1 < bL2) { bL2 = o1; jL2 = oj1; }
        if (o2 < bL2) { bL2 = o2; jL2 = oj2; }
        o1 = __shfl_xor_sync(0xFFFFFFFFu, bH1, d); oj1 = __shfl_xor_sync(0xFFFFFFFFu, jH1, d);
        o2 = __shfl_xor_sync(0xFFFFFFFFu, bH2, d); oj2 = __shfl_xor_sync(0xFFFFFFFFu, jH2, d);
        if (o1 < bH1) { float t = bH1; bH1 = o1; o1 = t; int ti = jH1; jH1 = oj1; oj1 = ti; }
        if (o1 < bH2) { bH2 = o1; jH2 = oj1; }
        if (o2 < bH2) { bH2 = o2; jH2 = oj2; }
    }
    if (q == 0) {
        int base = wid * 16 + g;
        sbj[base]      = jL1;  sbj2[base]     = jL2;
        sbj[base + 8]  = jH1;  sbj2[base + 8] = jH2;
    }
    __syncthreads();

    // ---- fp32-exact recheck + outputs: threads 0..127 own one row each ----
    float ls = 0.0f;
    if (tid < TILE_M) {
        const int row = tile * TILE_M + tid;
        int bj = sbj[tid], bj2 = sbj2[tid];
        const float4* xr = reinterpret_cast<const float4*>(X + (size_t)row * DC);
        const float4* e1 = reinterpret_cast<const float4*>(E + (size_t)bj * DC);
        const float4* e2 = reinterpret_cast<const float4*>(E + (size_t)bj2 * DC);
        float4 xf[DC / 4];
        float xsq = 0.0f, dot1 = 0.0f, dot2 = 0.0f;
#pragma unroll
        for (int i = 0; i < DC / 4; i++) {
            float4 xv = xr[i]; xf[i] = xv;
            float4 a = e1[i], b = e2[i];
            xsq  += xv.x * xv.x + xv.y * xv.y + xv.z * xv.z + xv.w * xv.w;
            dot1 += xv.x * a.x + xv.y * a.y + xv.z * a.z + xv.w * a.w;
            dot2 += xv.x * b.x + xv.y * b.y + xv.z * b.z + xv.w * b.w;
        }
        float d1 = fmaf(-2.0f, dot1, sesq[bj]);
        float d2 = fmaf(-2.0f, dot2, sesq[bj2]);
        if (d2 < d1 || (d2 == d1 && bj2 < bj)) { bj = bj2; d1 = d2; }
        float mind = xsq + d1;

        const float4* ef = reinterpret_cast<const float4*>(E + (size_t)bj * DC);
        float4* zp = reinterpret_cast<float4*>(out + OFF_Z + (size_t)row * DC);
        float* sp = g_sums + (size_t)bj * DC;
#pragma unroll
        for (int i = 0; i < DC / 4; i++) {
            float4 ev = ef[i];
            zp[i] = ev;
            float dx = xf[i].x - ev.x, dy = xf[i].y - ev.y;
            float dz = xf[i].z - ev.z, dw = xf[i].w - ev.w;
            ls += dx * dx + dy * dy + dz * dz + dw * dw;
            atomicAdd(sp + i * 4 + 0, xf[i].x);
            atomicAdd(sp + i * 4 + 1, xf[i].y);
            atomicAdd(sp + i * 4 + 2, xf[i].z);
            atomicAdd(sp + i * 4 + 3, xf[i].w);
        }
        atomicAdd(&g_counts[bj], 1.0f);

        out[OFF_ARG + row] = (float)bj;
        out[OFF_MIN + row] = mind;
    }

    // loss reduction over all 256 threads (upper half contributes 0)
#pragma unroll
    for (int s = 16; s > 0; s >>= 1)
        ls += __shfl_xor_sync(0xFFFFFFFFu, ls, s);
    if (lane == 0) swred[wid] = ls;
    __syncthreads();
    if (wid == 0) {
        float v = (lane < ATPB / 32) ? swred[lane] : 0.0f;
#pragma unroll
        for (int s = 4; s > 0; s >>= 1)
            v += __shfl_xor_sync(0xFFFFFFFFu, v, s);
        if (lane == 0) atomicAdd(&g_minsum, v);
    }
}

// ---------------------------------------------------------------------------
// Kernel 3: EMA finalize — cs, ma, E_new, loss (one block of KC threads)
// ---------------------------------------------------------------------------
__global__ void vq_finalize_kernel(
    const float* __restrict__ cluster_sizes,
    const float* __restrict__ moving_avg,
    float* __restrict__ out)
{
    __shared__ float red[KC];
    const int k = threadIdx.x;

    float c = GAMMA * cluster_sizes[k] + (1.0f - GAMMA) * g_counts[k];
    red[k] = c;
    __syncthreads();
    for (int s = KC / 2; s > 0; s >>= 1) {
        if (k < s) red[k] += red[k + s];
        __syncthreads();
    }
    float scs = red[0];

    float cs = (c + ALPHA) / (1.0f + ALPHA * (float)KC / scs);
    out[OFF_CS + k] = cs;
    float inv = 1.0f / cs;

    const float4* mav = reinterpret_cast<const float4*>(moving_avg + (size_t)k * DC);
    const float4* sv  = reinterpret_cast<const float4*>(g_sums + (size_t)k * DC);
    float* map = out + OFF_MA + (size_t)k * DC;
    float* enp = out + OFF_EN + (size_t)k * DC;
#pragma unroll
    for (int i = 0; i < DC / 4; i++) {
        float4 m = mav[i];
        float4 s4 = sv[i];
        float a  = GAMMA * m.x + (1.0f - GAMMA) * s4.x;
        float b  = GAMMA * m.y + (1.0f - GAMMA) * s4.y;
        float cz = GAMMA * m.z + (1.0f - GAMMA) * s4.z;
        float d  = GAMMA * m.w + (1.0f - GAMMA) * s4.w;
        map[i * 4 + 0] = a;  map[i * 4 + 1] = b;
        map[i * 4 + 2] = cz; map[i * 4 + 3] = d;
        enp[i * 4 + 0] = a * inv;  enp[i * 4 + 1] = b * inv;
        enp[i * 4 + 2] = cz * inv; enp[i * 4 + 3] = d * inv;
    }

    if (k == 0) out[OFF_LOSS] = BETA * g_minsum / (float)NC;
}

// ---------------------------------------------------------------------------
// Launch
// ---------------------------------------------------------------------------
extern "C" void kernel_launch(void* const* d_in, const int* in_sizes, int n_in,
                              void* d_out, int out_size)
{
    const float* X  = (const float*)d_in[0];
    const float* E  = (const float*)d_in[1];
    const float* CS = (const float*)d_in[2];
    const float* MA = (const float*)d_in[3];
    float* out = (float*)d_out;

    vq_prep<<<64, 1024>>>(E);
    vq_assign_mma<<<NTILES, ATPB>>>(X, E, out);
    vq_finalize_kernel<<<1, KC>>>(CS, MA, out);
}

// round 15
// speedup vs baseline: 2.1168x; 1.0634x over previous
#include <cuda_runtime.h>
#include <cuda_fp16.h>
#include <cstdint>

// Problem constants
#define KC    1024
#define DC    64
#define NC    131072
#define GAMMA 0.99f
#define ALPHA 1e-9f
#define BETA  0.25f

// Output layout (float32, concatenated in reference tuple order)
// OFF_EN / OFF_MA are NOT 16B-aligned -> scalar stores only there.
#define OFF_Z    0
#define OFF_LOSS 8388608
#define OFF_ARG  8388609
#define OFF_MIN  8519681
#define OFF_EN   8650753
#define OFF_CS   8716289
#define OFF_MA   8717313

#define TILE_M   128
#define NTILES   (NC / TILE_M)        // 1024 CTAs
#define ATPB     256                  // 8 warps
#define CH_K     128                  // codes per E chunk
#define NCHUNKS  (KC / CH_K)          // 8
#define ROWW     36                   // padded smem row stride in u32 (72 fp16)

// Device scratch (no allocation allowed)
__device__ __align__(16) float g_sums[KC * DC];
__device__ float g_counts[KC];
__device__ float g_esq[KC];
__device__ float g_minsum;
// E fp16 image, row-major [code][d], packed 2 fp16 per u32
__device__ __align__(16) uint32_t g_ef16[KC * DC / 2];

__device__ __forceinline__ uint32_t packh2(float2 v) {
    __half2 h = __floats2half2_rn(v.x, v.y);
    return *reinterpret_cast<uint32_t*>(&h);
}

// m16n8k16 fp16 MMA, f32 accumulate (base PTX, sm_80+; SASS = HMMA)
__device__ __forceinline__ void mma16816(float& c0, float& c1, float& c2, float& c3,
                                         uint32_t a0, uint32_t a1, uint32_t a2, uint32_t a3,
                                         uint32_t b0, uint32_t b1) {
    asm volatile(
        "mma.sync.aligned.m16n8k16.row.col.f32.f16.f16.f32 "
        "{%0,%1,%2,%3}, {%4,%5,%6,%7}, {%8,%9}, {%0,%1,%2,%3};"
        : "+f"(c0), "+f"(c1), "+f"(c2), "+f"(c3)
        : "r"(a0), "r"(a1), "r"(a2), "r"(a3), "r"(b0), "r"(b1));
}

// ---------------------------------------------------------------------------
// Kernel 1: prep — zero scratch, esq, E fp16 image. 64 x 1024.
// ---------------------------------------------------------------------------
__global__ void vq_prep(const float* __restrict__ E) {
    int i = blockIdx.x * blockDim.x + threadIdx.x;   // [0, 65536)
    g_sums[i] = 0.0f;
    if (i == 0) g_minsum = 0.0f;
    if (i < KC) {
        g_counts[i] = 0.0f;
        const float4* e = reinterpret_cast<const float4*>(E + (size_t)i * DC);
        float s = 0.0f;
#pragma unroll
        for (int j = 0; j < DC / 4; j++) {
            float4 v = e[j];
            s += v.x * v.x + v.y * v.y + v.z * v.z + v.w * v.w;
        }
        g_esq[i] = s;
    }
    if (i < KC * DC / 2) {               // 32768 pairs
        const float2* e2 = reinterpret_cast<const float2*>(E);
        g_ef16[i] = packh2(e2[i]);
    }
}

// ---------------------------------------------------------------------------
// Kernel 2: assignment via 1-pass fp16 mma.sync — 128 rows/CTA, 8 warps x m16,
// per-lane local top-2 (8 candidates/row), fp32-exact recheck of all 8
// ---------------------------------------------------------------------------
__global__ void __launch_bounds__(ATPB, 2)
vq_assign_mma(const float* __restrict__ X, const float* __restrict__ E,
              float* __restrict__ out)
{
    __shared__ uint32_t seh[CH_K * ROWW];       // 18432 B
    __shared__ float    sesq[KC];               // 4096 B
    __shared__ int      s1[TILE_M * 4];         // per-lane local best
    __shared__ int      s2[TILE_M * 4];         // per-lane local 2nd
    __shared__ float    swred[ATPB / 32];

    const int tid  = threadIdx.x;
    const int tile = blockIdx.x;
    const int wid  = tid >> 5;
    const int lane = tid & 31;
    const int g    = lane >> 2;        // groupID: 0..7
    const int q    = lane & 3;         // thread-in-group

    // esq -> smem
    for (int i = tid; i < KC; i += ATPB) sesq[i] = g_esq[i];

    // A fragments: fp16-pack X rows straight from global.
    const int rl = tile * TILE_M + wid * 16 + g;
    const int rh = rl + 8;
    uint32_t xa[4][4];
    {
        const float2* X2 = reinterpret_cast<const float2*>(X);
#pragma unroll
        for (int ks = 0; ks < 4; ks++) {
            int k0 = ks * 8 + q;       // float2 index within row
            xa[ks][0] = packh2(X2[(size_t)rl * 32 + k0]);
            xa[ks][1] = packh2(X2[(size_t)rh * 32 + k0]);
            xa[ks][2] = packh2(X2[(size_t)rl * 32 + k0 + 4]);
            xa[ks][3] = packh2(X2[(size_t)rh * 32 + k0 + 4]);
        }
    }

    // per-lane local top-2 for row L and row H
    float bL1 = 3.4e38f, bL2 = 3.4e38f, bH1 = 3.4e38f, bH2 = 3.4e38f;
    int   jL1 = 0, jL2 = 0, jH1 = 0, jH2 = 0;

    const uint4* gEh = reinterpret_cast<const uint4*>(g_ef16);

    for (int cc = 0; cc < NCHUNKS; cc++) {
        __syncthreads();
        // stage E chunk into padded smem (conflict-free rows of 144 B)
        for (int i = tid; i < CH_K * 8; i += ATPB) {
            int row = i >> 3, qq = i & 7;
            uint4 vh = gEh[(size_t)(cc * CH_K + row) * 8 + qq];
            *reinterpret_cast<uint4*>(&seh[row * ROWW + qq * 4]) = vh;
        }
        __syncthreads();

        // double-buffered B fragments
        uint32_t bh[2][8];
        {
            const uint32_t* bhr = &seh[g * ROWW];
#pragma unroll
            for (int ks = 0; ks < 4; ks++) {
                int w = ks * 8 + q;
                bh[0][2 * ks]     = bhr[w];
                bh[0][2 * ks + 1] = bhr[w + 4];
            }
        }

#pragma unroll 4
        for (int nt = 0; nt < CH_K / 8; nt++) {
            const int cur = nt & 1, nxt = cur ^ 1;
            if (nt < CH_K / 8 - 1) {
                const uint32_t* bhr = &seh[((nt + 1) * 8 + g) * ROWW];
#pragma unroll
                for (int ks = 0; ks < 4; ks++) {
                    int w = ks * 8 + q;
                    bh[nxt][2 * ks]     = bhr[w];
                    bh[nxt][2 * ks + 1] = bhr[w + 4];
                }
            }

            float c0 = 0.f, c1 = 0.f, c2 = 0.f, c3 = 0.f;
#pragma unroll
            for (int ks = 0; ks < 4; ks++)
                mma16816(c0, c1, c2, c3, xa[ks][0], xa[ks][1], xa[ks][2], xa[ks][3],
                         bh[cur][2 * ks], bh[cur][2 * ks + 1]);

            int col0 = cc * CH_K + nt * 8 + q * 2;
            int col1 = col0 + 1;
            float p;
            p = fmaf(-2.0f, c0, sesq[col0]);
            if (p < bL1) { bL2 = bL1; jL2 = jL1; bL1 = p; jL1 = col0; }
            else if (p < bL2) { bL2 = p; jL2 = col0; }
            p = fmaf(-2.0f, c1, sesq[col1]);
            if (p < bL1) { bL2 = bL1; jL2 = jL1; bL1 = p; jL1 = col1; }
            else if (p < bL2) { bL2 = p; jL2 = col1; }
            p = fmaf(-2.0f, c2, sesq[col0]);
            if (p < bH1) { bH2 = bH1; jH2 = jH1; bH1 = p; jH1 = col0; }
            else if (p < bH2) { bH2 = p; jH2 = col0; }
            p = fmaf(-2.0f, c3, sesq[col1]);
            if (p < bH1) { bH2 = bH1; jH2 = jH1; bH1 = p; jH1 = col1; }
            else if (p < bH2) { bH2 = p; jH2 = col1; }
        }
    }

    // store per-lane local top-2 (no merge; 4 lanes x 2 = 8 candidates/row)
    {
        int baseL = (wid * 16 + g) * 4 + q;
        int baseH = (wid * 16 + g + 8) * 4 + q;
        s1[baseL] = jL1;  s2[baseL] = jL2;
        s1[baseH] = jH1;  s2[baseH] = jH2;
    }
    __syncthreads();

    // ---- fp32-exact recheck of 8 candidates: threads 0..127 own one row ----
    float ls = 0.0f;
    if (tid < TILE_M) {
        const int row = tile * TILE_M + tid;
        int cand[8];
#pragma unroll
        for (int c = 0; c < 4; c++) {
            cand[c]     = s1[tid * 4 + c];
            cand[c + 4] = s2[tid * 4 + c];
        }
        const float4* xr = reinterpret_cast<const float4*>(X + (size_t)row * DC);
        float4 xf[DC / 4];
        float xsq = 0.0f;
#pragma unroll
        for (int i = 0; i < DC / 4; i++) {
            float4 xv = xr[i]; xf[i] = xv;
            xsq += xv.x * xv.x + xv.y * xv.y + xv.z * xv.z + xv.w * xv.w;
        }
        float bd = 3.4e38f;
        int   bj = KC;
#pragma unroll
        for (int c = 0; c < 8; c++) {
            int j = cand[c];
            const float4* er = reinterpret_cast<const float4*>(E + (size_t)j * DC);
            float dot = 0.0f;
#pragma unroll
            for (int i = 0; i < DC / 4; i++) {
                float4 ev = er[i];
                dot += xf[i].x * ev.x + xf[i].y * ev.y
                     + xf[i].z * ev.z + xf[i].w * ev.w;
            }
            float d = fmaf(-2.0f, dot, sesq[j]);
            if (d < bd || (d == bd && j < bj)) { bd = d; bj = j; }
        }
        float mind = xsq + bd;

        const float4* ef = reinterpret_cast<const float4*>(E + (size_t)bj * DC);
        float4* zp = reinterpret_cast<float4*>(out + OFF_Z + (size_t)row * DC);
        float* sp = g_sums + (size_t)bj * DC;
#pragma unroll
        for (int i = 0; i < DC / 4; i++) {
            float4 ev = ef[i];
            zp[i] = ev;
            float dx = xf[i].x - ev.x, dy = xf[i].y - ev.y;
            float dz = xf[i].z - ev.z, dw = xf[i].w - ev.w;
            ls += dx * dx + dy * dy + dz * dz + dw * dw;
            atomicAdd(sp + i * 4 + 0, xf[i].x);
            atomicAdd(sp + i * 4 + 1, xf[i].y);
            atomicAdd(sp + i * 4 + 2, xf[i].z);
            atomicAdd(sp + i * 4 + 3, xf[i].w);
        }
        atomicAdd(&g_counts[bj], 1.0f);

        out[OFF_ARG + row] = (float)bj;
        out[OFF_MIN + row] = mind;
    }

    // loss reduction over all 256 threads (upper half contributes 0)
#pragma unroll
    for (int s = 16; s > 0; s >>= 1)
        ls += __shfl_xor_sync(0xFFFFFFFFu, ls, s);
    if (lane == 0) swred[wid] = ls;
    __syncthreads();
    if (wid == 0) {
        float v = (lane < ATPB / 32) ? swred[lane] : 0.0f;
#pragma unroll
        for (int s = 4; s > 0; s >>= 1)
            v += __shfl_xor_sync(0xFFFFFFFFu, v, s);
        if (lane == 0) atomicAdd(&g_minsum, v);
    }
}

// ---------------------------------------------------------------------------
// Kernel 3: EMA finalize — cs, ma, E_new, loss (one block of KC threads)
// ---------------------------------------------------------------------------
__global__ void vq_finalize_kernel(
    const float* __restrict__ cluster_sizes,
    const float* __restrict__ moving_avg,
    float* __restrict__ out)
{
    __shared__ float red[KC];
    const int k = threadIdx.x;

    float c = GAMMA * cluster_sizes[k] + (1.0f - GAMMA) * g_counts[k];
    red[k] = c;
    __syncthreads();
    for (int s = KC / 2; s > 0; s >>= 1) {
        if (k < s) red[k] += red[k + s];
        __syncthreads();
    }
    float scs = red[0];

    float cs = (c + ALPHA) / (1.0f + ALPHA * (float)KC / scs);
    out[OFF_CS + k] = cs;
    float inv = 1.0f / cs;

    const float4* mav = reinterpret_cast<const float4*>(moving_avg + (size_t)k * DC);
    const float4* sv  = reinterpret_cast<const float4*>(g_sums + (size_t)k * DC);
    float* map = out + OFF_MA + (size_t)k * DC;
    float* enp = out + OFF_EN + (size_t)k * DC;
#pragma unroll
    for (int i = 0; i < DC / 4; i++) {
        float4 m = mav[i];
        float4 s4 = sv[i];
        float a  = GAMMA * m.x + (1.0f - GAMMA) * s4.x;
        float b  = GAMMA * m.y + (1.0f - GAMMA) * s4.y;
        float cz = GAMMA * m.z + (1.0f - GAMMA) * s4.z;
        float d  = GAMMA * m.w + (1.0f - GAMMA) * s4.w;
        map[i * 4 + 0] = a;  map[i * 4 + 1] = b;
        map[i * 4 + 2] = cz; map[i * 4 + 3] = d;
        enp[i * 4 + 0] = a * inv;  enp[i * 4 + 1] = b * inv;
        enp[i * 4 + 2] = cz * inv; enp[i * 4 + 3] = d * inv;
    }

    if (k == 0) out[OFF_LOSS] = BETA * g_minsum / (float)NC;
}

// ---------------------------------------------------------------------------
// Launch
// ---------------------------------------------------------------------------
extern "C" void kernel_launch(void* const* d_in, const int* in_sizes, int n_in,
                              void* d_out, int out_size)
{
    const float* X  = (const float*)d_in[0];
    const float* E  = (const float*)d_in[1];
    const float* CS = (const float*)d_in[2];
    const float* MA = (const float*)d_in[3];
    float* out = (float*)d_out;

    vq_prep<<<64, 1024>>>(E);
    vq_assign_mma<<<NTILES, ATPB>>>(X, E, out);
    vq_finalize_kernel<<<1, KC>>>(CS, MA, out);
}

// round 17
// speedup vs baseline: 3.0523x; 1.4419x over previous
#include <cuda_runtime.h>
#include <cuda_fp16.h>
#include <cstdint>

// Problem constants
#define KC    1024
#define DC    64
#define NC    131072
#define GAMMA 0.99f
#define ALPHA 1e-9f
#define BETA  0.25f

// Output layout (float32, concatenated in reference tuple order)
// OFF_EN / OFF_MA are NOT 16B-aligned -> scalar stores only there.
#define OFF_Z    0
#define OFF_LOSS 8388608
#define OFF_ARG  8388609
#define OFF_MIN  8519681
#define OFF_EN   8650753
#define OFF_CS   8716289
#define OFF_MA   8717313

#define TILE_M   128
#define NTILES   (NC / TILE_M)        // 1024 CTAs
#define ATPB     256                  // 8 warps
#define CH_K     128                  // codes per E chunk
#define NCHUNKS  (KC / CH_K)          // 8
#define ROWW     36                   // padded smem row stride in u32 (72 fp16)
#define FINB     8                    // finalize blocks

// Device scratch (no allocation allowed)
__device__ __align__(16) float g_sums[KC * DC];
__device__ float g_counts[KC];
__device__ float g_esq[KC];
__device__ float g_minsum;
// E fp16 image, row-major [code][d], packed 2 fp16 per u32
__device__ __align__(16) uint32_t g_ef16[KC * DC / 2];

__device__ __forceinline__ uint32_t packh2(float2 v) {
    __half2 h = __floats2half2_rn(v.x, v.y);
    return *reinterpret_cast<uint32_t*>(&h);
}

// ordered-uint key: monotone in p, low 10 bits carry the code index
__device__ __forceinline__ uint32_t mkkey(float p, int col) {
    uint32_t b = __float_as_uint(p);
    uint32_t m = (uint32_t)(((int32_t)b) >> 31) | 0x80000000u;
    b ^= m;
    return (b & 0xFFFFFC00u) | (uint32_t)col;
}

// m16n8k16 fp16 MMA, f32 accumulate (base PTX, sm_80+; SASS = HMMA)
__device__ __forceinline__ void mma16816(float& c0, float& c1, float& c2, float& c3,
                                         uint32_t a0, uint32_t a1, uint32_t a2, uint32_t a3,
                                         uint32_t b0, uint32_t b1) {
    asm volatile(
        "mma.sync.aligned.m16n8k16.row.col.f32.f16.f16.f32 "
        "{%0,%1,%2,%3}, {%4,%5,%6,%7}, {%8,%9}, {%0,%1,%2,%3};"
        : "+f"(c0), "+f"(c1), "+f"(c2), "+f"(c3)
        : "r"(a0), "r"(a1), "r"(a2), "r"(a3), "r"(b0), "r"(b1));
}

// ---------------------------------------------------------------------------
// Kernel 1: prep — zero scratch, esq, E fp16 image. 64 x 1024.
// ---------------------------------------------------------------------------
__global__ void vq_prep(const float* __restrict__ E) {
    int i = blockIdx.x * blockDim.x + threadIdx.x;   // [0, 65536)
    g_sums[i] = 0.0f;
    if (i == 0) g_minsum = 0.0f;
    if (i < KC) {
        g_counts[i] = 0.0f;
        const float4* e = reinterpret_cast<const float4*>(E + (size_t)i * DC);
        float s = 0.0f;
#pragma unroll
        for (int j = 0; j < DC / 4; j++) {
            float4 v = e[j];
            s += v.x * v.x + v.y * v.y + v.z * v.z + v.w * v.w;
        }
        g_esq[i] = s;
    }
    if (i < KC * DC / 2) {               // 32768 pairs
        const float2* e2 = reinterpret_cast<const float2*>(E);
        g_ef16[i] = packh2(e2[i]);
    }
}

// ---------------------------------------------------------------------------
// Kernel 2: assignment via 1-pass fp16 mma.sync — 128 rows/CTA, 8 warps x m16,
// BRANCHLESS per-lane top-2 keys, fp32-exact recheck of 8 deduped candidates
// ---------------------------------------------------------------------------
__global__ void __launch_bounds__(ATPB, 2)
vq_assign_mma(const float* __restrict__ X, const float* __restrict__ E,
              float* __restrict__ out)
{
    __shared__ uint32_t seh[CH_K * ROWW];       // 18432 B
    __shared__ float    sesq[KC];               // 4096 B
    __shared__ int      s1[TILE_M * 4];         // per-lane local best
    __shared__ int      s2[TILE_M * 4];         // per-lane local 2nd
    __shared__ float    swred[ATPB / 32];

    const int tid  = threadIdx.x;
    const int tile = blockIdx.x;
    const int wid  = tid >> 5;
    const int lane = tid & 31;
    const int g    = lane >> 2;        // groupID: 0..7
    const int q    = lane & 3;         // thread-in-group

    // esq -> smem
    for (int i = tid; i < KC; i += ATPB) sesq[i] = g_esq[i];

    // A fragments: fp16-pack X rows straight from global.
    const int rl = tile * TILE_M + wid * 16 + g;
    const int rh = rl + 8;
    uint32_t xa[4][4];
    {
        const float2* X2 = reinterpret_cast<const float2*>(X);
#pragma unroll
        for (int ks = 0; ks < 4; ks++) {
            int k0 = ks * 8 + q;       // float2 index within row
            xa[ks][0] = packh2(X2[(size_t)rl * 32 + k0]);
            xa[ks][1] = packh2(X2[(size_t)rh * 32 + k0]);
            xa[ks][2] = packh2(X2[(size_t)rl * 32 + k0 + 4]);
            xa[ks][3] = packh2(X2[(size_t)rh * 32 + k0 + 4]);
        }
    }

    // branchless per-lane top-2 keys for row L and row H
    uint32_t kL1 = 0xFFFFFFFFu, kL2 = 0xFFFFFFFFu;
    uint32_t kH1 = 0xFFFFFFFFu, kH2 = 0xFFFFFFFFu;

    const uint4* gEh = reinterpret_cast<const uint4*>(g_ef16);

    for (int cc = 0; cc < NCHUNKS; cc++) {
        __syncthreads();
        // stage E chunk into padded smem (conflict-free rows of 144 B)
        for (int i = tid; i < CH_K * 8; i += ATPB) {
            int row = i >> 3, qq = i & 7;
            uint4 vh = gEh[(size_t)(cc * CH_K + row) * 8 + qq];
            *reinterpret_cast<uint4*>(&seh[row * ROWW + qq * 4]) = vh;
        }
        __syncthreads();

        // double-buffered B fragments
        uint32_t bh[2][8];
        {
            const uint32_t* bhr = &seh[g * ROWW];
#pragma unroll
            for (int ks = 0; ks < 4; ks++) {
                int w = ks * 8 + q;
                bh[0][2 * ks]     = bhr[w];
                bh[0][2 * ks + 1] = bhr[w + 4];
            }
        }

#pragma unroll 4
        for (int nt = 0; nt < CH_K / 8; nt++) {
            const int cur = nt & 1, nxt = cur ^ 1;
            if (nt < CH_K / 8 - 1) {
                const uint32_t* bhr = &seh[((nt + 1) * 8 + g) * ROWW];
#pragma unroll
                for (int ks = 0; ks < 4; ks++) {
                    int w = ks * 8 + q;
                    bh[nxt][2 * ks]     = bhr[w];
                    bh[nxt][2 * ks + 1] = bhr[w + 4];
                }
            }

            float c0 = 0.f, c1 = 0.f, c2 = 0.f, c3 = 0.f;
#pragma unroll
            for (int ks = 0; ks < 4; ks++)
                mma16816(c0, c1, c2, c3, xa[ks][0], xa[ks][1], xa[ks][2], xa[ks][3],
                         bh[cur][2 * ks], bh[cur][2 * ks + 1]);

            int col0 = cc * CH_K + nt * 8 + q * 2;
            int col1 = col0 + 1;
            uint32_t u;
            u = mkkey(fmaf(-2.0f, c0, sesq[col0]), col0);
            kL2 = umin(kL2, umax(kL1, u));  kL1 = umin(kL1, u);
            u = mkkey(fmaf(-2.0f, c1, sesq[col1]), col1);
            kL2 = umin(kL2, umax(kL1, u));  kL1 = umin(kL1, u);
            u = mkkey(fmaf(-2.0f, c2, sesq[col0]), col0);
            kH2 = umin(kH2, umax(kH1, u));  kH1 = umin(kH1, u);
            u = mkkey(fmaf(-2.0f, c3, sesq[col1]), col1);
            kH2 = umin(kH2, umax(kH1, u));  kH1 = umin(kH1, u);
        }
    }

    // store per-lane local top-2 (no merge; 4 lanes x 2 = 8 candidates/row)
    {
        int baseL = (wid * 16 + g) * 4 + q;
        int baseH = (wid * 16 + g + 8) * 4 + q;
        s1[baseL] = (int)(kL1 & 1023u);  s2[baseL] = (int)(kL2 & 1023u);
        s1[baseH] = (int)(kH1 & 1023u);  s2[baseH] = (int)(kH2 & 1023u);
    }
    __syncthreads();

    // ---- fp32-exact recheck of deduped candidates; threads 0..127 ----
    float ls = 0.0f;
    if (tid < TILE_M) {
        const int row = tile * TILE_M + tid;
        int cand[8];
#pragma unroll
        for (int c = 0; c < 4; c++) {
            cand[c]     = s1[tid * 4 + c];
            cand[c + 4] = s2[tid * 4 + c];
        }
        const float4* xr = reinterpret_cast<const float4*>(X + (size_t)row * DC);
        float4 xf[DC / 4];
        float xsq = 0.0f;
#pragma unroll
        for (int i = 0; i < DC / 4; i++) {
            float4 xv = xr[i]; xf[i] = xv;
            xsq += xv.x * xv.x + xv.y * xv.y + xv.z * xv.z + xv.w * xv.w;
        }
        float bd = 3.4e38f;
        int   bj = KC;
#pragma unroll
        for (int c = 0; c < 8; c++) {
            int j = cand[c];
            bool dup = false;
#pragma unroll
            for (int cc2 = 0; cc2 < 8; cc2++)
                if (cc2 < c) dup |= (cand[cc2] == j);
            if (!dup) {
                const float4* er = reinterpret_cast<const float4*>(E + (size_t)j * DC);
                float dot = 0.0f;
#pragma unroll
                for (int i = 0; i < DC / 4; i++) {
                    float4 ev = er[i];
                    dot += xf[i].x * ev.x + xf[i].y * ev.y
                         + xf[i].z * ev.z + xf[i].w * ev.w;
                }
                float d = fmaf(-2.0f, dot, sesq[j]);
                if (d < bd || (d == bd && j < bj)) { bd = d; bj = j; }
            }
        }
        float mind = xsq + bd;

        const float4* ef = reinterpret_cast<const float4*>(E + (size_t)bj * DC);
        float4* zp = reinterpret_cast<float4*>(out + OFF_Z + (size_t)row * DC);
        float* sp = g_sums + (size_t)bj * DC;
#pragma unroll
        for (int i = 0; i < DC / 4; i++) {
            float4 ev = ef[i];
            zp[i] = ev;
            float dx = xf[i].x - ev.x, dy = xf[i].y - ev.y;
            float dz = xf[i].z - ev.z, dw = xf[i].w - ev.w;
            ls += dx * dx + dy * dy + dz * dz + dw * dw;
            atomicAdd(sp + i * 4 + 0, xf[i].x);
            atomicAdd(sp + i * 4 + 1, xf[i].y);
            atomicAdd(sp + i * 4 + 2, xf[i].z);
            atomicAdd(sp + i * 4 + 3, xf[i].w);
        }
        atomicAdd(&g_counts[bj], 1.0f);

        out[OFF_ARG + row] = (float)bj;
        out[OFF_MIN + row] = mind;
    }

    // loss reduction over all 256 threads (upper half contributes 0)
#pragma unroll
    for (int s = 16; s > 0; s >>= 1)
        ls += __shfl_xor_sync(0xFFFFFFFFu, ls, s);
    if (lane == 0) swred[wid] = ls;
    __syncthreads();
    if (wid == 0) {
        float v = (lane < ATPB / 32) ? swred[lane] : 0.0f;
#pragma unroll
        for (int s = 4; s > 0; s >>= 1)
            v += __shfl_xor_sync(0xFFFFFFFFu, v, s);
        if (lane == 0) atomicAdd(&g_minsum, v);
    }
}

// ---------------------------------------------------------------------------
// Kernel 3: EMA finalize — parallel: FINB blocks x 1024 threads.
// Each block reduces sum(cs) redundantly, then handles KC/FINB codes
// with 8 threads per code (8 dims each).
// ---------------------------------------------------------------------------
__global__ void vq_finalize_kernel(
    const float* __restrict__ cluster_sizes,
    const float* __restrict__ moving_avg,
    float* __restrict__ out)
{
    __shared__ float red[KC];
    const int t = threadIdx.x;

    float call = GAMMA * cluster_sizes[t] + (1.0f - GAMMA) * g_counts[t];
    red[t] = call;
    __syncthreads();
    for (int s = KC / 2; s > 0; s >>= 1) {
        if (t < s) red[t] += red[t + s];
        __syncthreads();
    }
    float scs = red[0];

    // this block's code slice: 8 threads per code, 8 dims per thread
    const int k  = blockIdx.x * (KC / FINB) + (t >> 3);
    const int d0 = (t & 7) * 8;

    float ck = GAMMA * cluster_sizes[k] + (1.0f - GAMMA) * g_counts[k];
    float cs = (ck + ALPHA) / (1.0f + ALPHA * (float)KC / scs);
    if ((t & 7) == 0) out[OFF_CS + k] = cs;
    float inv = 1.0f / cs;

    const float4* mav = reinterpret_cast<const float4*>(moving_avg + (size_t)k * DC + d0);
    const float4* sv  = reinterpret_cast<const float4*>(g_sums + (size_t)k * DC + d0);
    float* map = out + OFF_MA + (size_t)k * DC + d0;
    float* enp = out + OFF_EN + (size_t)k * DC + d0;
#pragma unroll
    for (int i = 0; i < 2; i++) {
        float4 m  = mav[i];
        float4 s4 = sv[i];
        float a  = GAMMA * m.x + (1.0f - GAMMA) * s4.x;
        float b  = GAMMA * m.y + (1.0f - GAMMA) * s4.y;
        float cz = GAMMA * m.z + (1.0f - GAMMA) * s4.z;
        float d  = GAMMA * m.w + (1.0f - GAMMA) * s4.w;
        map[i * 4 + 0] = a;  map[i * 4 + 1] = b;
        map[i * 4 + 2] = cz; map[i * 4 + 3] = d;
        enp[i * 4 + 0] = a * inv;  enp[i * 4 + 1] = b * inv;
        enp[i * 4 + 2] = cz * inv; enp[i * 4 + 3] = d * inv;
    }

    if (blockIdx.x == 0 && t == 0) out[OFF_LOSS] = BETA * g_minsum / (float)NC;
}

// ---------------------------------------------------------------------------
// Launch
// ---------------------------------------------------------------------------
extern "C" void kernel_launch(void* const* d_in, const int* in_sizes, int n_in,
                              void* d_out, int out_size)
{
    const float* X  = (const float*)d_in[0];
    const float* E  = (const float*)d_in[1];
    const float* CS = (const float*)d_in[2];
    const float* MA = (const float*)d_in[3];
    float* out = (float*)d_out;

    vq_prep<<<64, 1024>>>(E);
    vq_assign_mma<<<NTILES, ATPB>>>(X, E, out);
    vq_finalize_kernel<<<FINB, KC>>>(CS, MA, out);
}